// round 16
// baseline (speedup 1.0000x reference)
#include <cuda_runtime.h>
#include <cstdint>
#include <math.h>

#define Dk 128
#define Bk 1024
#define Rk 131072
#define NN 10
#define BN (Bk * NN)          // 10240
#define RNG 8                 // column ranges (stage-1 grid.x)
#define RSPAN (Rk / RNG)      // 16384 cols per CTA
#define SUB 128               // cols per sub-chunk
#define NSUB (RSPAN / SUB)    // 128
#define JBLK 16               // stage-2 j blocks
#define JW 640                // j per stage-2 block
#define QSCALE 254.0f         // fixed queue quant scale (127 / 0.5)

typedef unsigned long long u64;
typedef unsigned int u32;
typedef unsigned short u16;

// ---------------- device scratch ----------------
__device__ float g_feat[2][Bk * Dk];          // normalized fp32 feats [row][d]
__device__ u32   g_featQ[2][Bk * 32];         // int8 feats packed [row][kc]
__device__ u32   g_qQ[2][32][Rk];             // int8 queue packed [kc][r]
__device__ int   g_candV[2][Bk * RNG * NN];   // int top-10 values (sorted desc)
__device__ int   g_candI[2][Bk * RNG * NN];   // matching global col ids
__device__ int   g_topk[2][Bk * NN];
__device__ float g_nnT[2][Dk * BN];           // gathered fp32 [d][j]
__device__ float g_pS[2][Bk][JBLK];
__device__ float g_pP[2][Bk][JBLK];

// ---------------- helpers ----------------
__device__ __forceinline__ void ffma2(u64 &d, u64 a, u64 b) {
    asm("fma.rn.f32x2 %0, %1, %2, %0;" : "+l"(d) : "l"(a), "l"(b));
}
__device__ __forceinline__ u64 dupf(float f) {
    u64 r; unsigned u = __float_as_uint(f);
    asm("mov.b64 %0, {%1, %2};" : "=l"(r) : "r"(u), "r"(u));
    return r;
}
__device__ __forceinline__ float2 unpack2(u64 a) {
    float2 o;
    asm("mov.b64 {%0, %1}, %2;" : "=f"(o.x), "=f"(o.y) : "l"(a));
    return o;
}
__device__ __forceinline__ u32 smem_u32(const void* p) {
    u32 a;
    asm("{ .reg .u64 t; cvta.to.shared.u64 t, %1; cvt.u32.u64 %0, t; }"
        : "=r"(a) : "l"(p));
    return a;
}
#define CP_ASYNC16(sdst, gsrc) \
    asm volatile("cp.async.cg.shared.global [%0], [%1], 16;" \
                 :: "r"(sdst), "l"(gsrc) : "memory")
#define CP_COMMIT() asm volatile("cp.async.commit_group;" ::: "memory")
#define CP_WAIT0()  asm volatile("cp.async.wait_group 0;" ::: "memory")

// ---------------- 1. normalize rows + int8 pack ---------------------------------
__global__ void normalize_kernel(const float* __restrict__ fX,
                                 const float* __restrict__ fY) {
    int side = blockIdx.y;
    int row = blockIdx.x;
    int d = threadIdx.x;
    const float* in = side ? fY : fX;
    float v = in[row * Dk + d];
    float sq = v * v;
    #pragma unroll
    for (int o = 16; o; o >>= 1) sq += __shfl_xor_sync(0xFFFFFFFFu, sq, o);
    __shared__ float ws[4], wm[4];
    __shared__ float nrm, smx;
    __shared__ unsigned char sb8[128];
    if ((d & 31) == 0) ws[d >> 5] = sq;
    __syncthreads();
    if (d == 0) nrm = sqrtf(ws[0] + ws[1] + ws[2] + ws[3]);
    __syncthreads();
    float nv = v / nrm;
    g_feat[side][row * Dk + d] = nv;
    float av = fabsf(nv);
    #pragma unroll
    for (int o = 16; o; o >>= 1) av = fmaxf(av, __shfl_xor_sync(0xFFFFFFFFu, av, o));
    if ((d & 31) == 0) wm[d >> 5] = av;
    __syncthreads();
    if (d == 0) smx = fmaxf(fmaxf(wm[0], wm[1]), fmaxf(wm[2], wm[3]));
    __syncthreads();
    int q = __float2int_rn(nv * (127.f / smx));
    sb8[d] = (unsigned char)(signed char)q;
    __syncthreads();
    if (d < 32) {
        u32 p = (u32)sb8[4 * d] | ((u32)sb8[4 * d + 1] << 8) |
                ((u32)sb8[4 * d + 2] << 16) | ((u32)sb8[4 * d + 3] << 24);
        g_featQ[side][row * 32 + d] = p;   // [row][kc]
    }
}

// ---------------- 2. transpose + fixed-scale int8 quantize queue ----------------
__global__ void transposeQ_kernel(int side, const float* __restrict__ qX,
                                  const float* __restrict__ qY) {
    const float* src = side ? qX : qY;   // side 0 (feat X) uses queue_Y
    __shared__ float tile[32][33];
    int r0 = blockIdx.x * 32, d0 = blockIdx.y * 32;
    int tx = threadIdx.x, ty = threadIdx.y;
    #pragma unroll
    for (int i = 0; i < 4; ++i)
        tile[ty + i * 8][tx] = src[(size_t)(d0 + ty + i * 8) * Rk + r0 + tx];
    __syncthreads();
    u32 p = 0;
    #pragma unroll
    for (int b = 0; b < 4; ++b) {
        float v = fminf(fmaxf(tile[ty * 4 + b][tx] * QSCALE, -127.f), 127.f);
        int q = __float2int_rn(v);
        p |= ((u32)(unsigned char)(signed char)q) << (8 * b);
    }
    g_qQ[side][(d0 >> 2) + ty][r0 + tx] = p;
}

// ---------------- 3. DP4A sim GEMM + int Ss redistribution top-10 ---------------
#define S_QS 0                        // Qs u32 [2][32][128] = 32768 B
#define S_AS 32768                    // As u32 [64][32]     = 8192 B
#define S_SS 40960                    // Ss int [64][132]    = 33792 B
#define S_CV 74752                    // Cv int [256][10]    = 10240 B
#define S_CI 84992                    // Ci u16 [256][10]    = 5120 B
#define SMEM1 90112
#define SP1 132

__global__ void __launch_bounds__(256, 2) simtopk_i8_kernel(int side) {
    extern __shared__ char sm[];
    u32 sb = smem_u32(sm);
    u32* Qs = reinterpret_cast<u32*>(sm + S_QS);
    u32* As = reinterpret_cast<u32*>(sm + S_AS);
    int* Ss = reinterpret_cast<int*>(sm + S_SS);
    int* Cv = reinterpret_cast<int*>(sm + S_CV);
    u16* Ci = reinterpret_cast<u16*>(sm + S_CI);
    int t = threadIdx.x, tx = t & 15, ty = t >> 4;
    int range = blockIdx.x, rt = blockIdx.y;
    int colBase = range * RSPAN;

    // A tile: [64 rows][32 kc] contiguous copy
    {
        const uint4* src = reinterpret_cast<const uint4*>(&g_featQ[side][rt * 64 * 32]);
        reinterpret_cast<uint4*>(As)[t] = src[t];
        reinterpret_cast<uint4*>(As)[t + 256] = src[t + 256];
    }
    // init persistent lists: thread owns (row = t>>2, seg = t&3)
    int* myCv = Cv + t * 10;
    u16* myCi = Ci + t * 10;
    #pragma unroll
    for (int k = 0; k < NN; ++k) { myCv[k] = (int)0x80000000; myCi[k] = 0; }
    int tv9 = (int)0x80000000;

    // cp.async slot mapping: 4 x 16B of Qs per thread
    int kcA = t >> 3;
    int c4A = (t * 4) & 31;
    const char* gQbase = reinterpret_cast<const char*>(&g_qQ[side][0][0]);
    size_t qRowStride = (size_t)Rk * 4;
    u32 sQ0 = sb + S_QS + (u32)(kcA * 512 + c4A * 16);

    // prologue: tile 0 -> buf 0
    {
        const char* gsrc = gQbase + (size_t)kcA * qRowStride +
                           (size_t)(colBase + c4A * 4) * 4;
        #pragma unroll
        for (int j = 0; j < 4; ++j) CP_ASYNC16(sQ0 + j * 16, gsrc + j * 16);
        CP_COMMIT();
    }

    int row = t >> 2, seg = t & 3;
    const int* scanBase = Ss + row * SP1 + seg * 32;

    for (int sc = 0; sc < NSUB; ++sc) {
        CP_WAIT0();
        __syncthreads();   // tile sc visible; prev scan's Ss reads done

        // prefetch tile sc+1 into alternate buffer (overlaps mainloop)
        if (sc + 1 < NSUB) {
            const char* gsrc = gQbase + (size_t)kcA * qRowStride +
                               (size_t)(colBase + (sc + 1) * SUB + c4A * 4) * 4;
            u32 sdst = sQ0 + (u32)(((sc + 1) & 1) * 16384);
            #pragma unroll
            for (int j = 0; j < 4; ++j) CP_ASYNC16(sdst + j * 16, gsrc + j * 16);
        }
        CP_COMMIT();

        const u32* Qb = Qs + (sc & 1) * 4096;

        // mainloop: 4 rows x 8 cols, A via LDS.128 broadcast
        int acc[4][8];
        #pragma unroll
        for (int r = 0; r < 4; ++r)
            #pragma unroll
            for (int c = 0; c < 8; ++c) acc[r][c] = 0;

        #pragma unroll 2
        for (int k4 = 0; k4 < 8; ++k4) {
            uint4 a4[4];
            #pragma unroll
            for (int r = 0; r < 4; ++r)
                a4[r] = *reinterpret_cast<const uint4*>(As + (ty * 4 + r) * 32 + k4 * 4);
            #pragma unroll
            for (int kk = 0; kk < 4; ++kk) {
                const u32* qp = Qb + (k4 * 4 + kk) * 128 + tx * 4;
                uint4 q0 = *reinterpret_cast<const uint4*>(qp);
                uint4 q1 = *reinterpret_cast<const uint4*>(qp + 64);
                #pragma unroll
                for (int r = 0; r < 4; ++r) {
                    int f = (int)((kk == 0) ? a4[r].x : (kk == 1) ? a4[r].y
                                 : (kk == 2) ? a4[r].z : a4[r].w);
                    acc[r][0] = __dp4a((int)q0.x, f, acc[r][0]);
                    acc[r][1] = __dp4a((int)q0.y, f, acc[r][1]);
                    acc[r][2] = __dp4a((int)q0.z, f, acc[r][2]);
                    acc[r][3] = __dp4a((int)q0.w, f, acc[r][3]);
                    acc[r][4] = __dp4a((int)q1.x, f, acc[r][4]);
                    acc[r][5] = __dp4a((int)q1.y, f, acc[r][5]);
                    acc[r][6] = __dp4a((int)q1.z, f, acc[r][6]);
                    acc[r][7] = __dp4a((int)q1.w, f, acc[r][7]);
                }
            }
        }

        // write raw int accumulators to Ss (8 STS.128)
        #pragma unroll
        for (int g = 0; g < 2; ++g)
            #pragma unroll
            for (int r = 0; r < 4; ++r) {
                int4 w = make_int4(acc[r][g * 4 + 0], acc[r][g * 4 + 1],
                                   acc[r][g * 4 + 2], acc[r][g * 4 + 3]);
                *reinterpret_cast<int4*>(Ss + (ty * 4 + r) * SP1 + g * 64 + tx * 4) = w;
            }
        __syncthreads();   // Ss visible

        // scan: contiguous 32 cols via 8 LDS.128 + quad-max prefilter
        {
            int cb = sc * SUB + seg * 32;
            #pragma unroll
            for (int qd = 0; qd < 8; ++qd) {
                int4 v = *reinterpret_cast<const int4*>(scanBase + qd * 4);
                int m01 = max(v.x, v.y), m23 = max(v.z, v.w);
                if (max(m01, m23) > tv9) {
                    int vv[4] = { v.x, v.y, v.z, v.w };
                    #pragma unroll
                    for (int e = 0; e < 4; ++e) {
                        int val = vv[e];
                        if (val > tv9) {
                            u16 col = (u16)(cb + qd * 4 + e);
                            int pp = 9;
                            while (pp > 0 && myCv[pp - 1] < val) {
                                myCv[pp] = myCv[pp - 1]; myCi[pp] = myCi[pp - 1]; --pp;
                            }
                            myCv[pp] = val; myCi[pp] = col;
                            tv9 = myCv[9];
                        }
                    }
                }
            }
        }
    }
    __syncthreads();

    // merge 4 seg-lists per row -> sorted top-10 -> g_cand (scratch in Qs)
    if (t < 64) {
        int* mv = reinterpret_cast<int*>(Qs) + t * 16;
        int* mi = reinterpret_cast<int*>(Qs) + 1024 + t * 16;
        #pragma unroll
        for (int k = 0; k < NN; ++k) { mv[k] = (int)0x80000000; mi[k] = 0x7fffffff; }
        int m9 = (int)0x80000000; int i9 = 0x7fffffff;
        for (int s = 0; s < 4; ++s) {
            const int* l = Cv + (t * 4 + s) * 10;
            const u16* li = Ci + (t * 4 + s) * 10;
            #pragma unroll
            for (int k = 0; k < NN; ++k) {
                int v = l[k];
                if (v < m9) break;
                int id = (int)li[k];
                if (v == m9 && id >= i9) continue;
                int pp = 9;
                while (pp > 0 && (mv[pp - 1] < v ||
                                  (mv[pp - 1] == v && mi[pp - 1] > id))) {
                    mv[pp] = mv[pp - 1]; mi[pp] = mi[pp - 1]; --pp;
                }
                mv[pp] = v; mi[pp] = id;
                m9 = mv[9]; i9 = mi[9];
            }
        }
        size_t gb = (((size_t)(rt * 64 + t) * RNG) + range) * NN;
        #pragma unroll
        for (int k = 0; k < NN; ++k) {
            g_candV[side][gb + k] = mv[k];
            g_candI[side][gb + k] = colBase + mi[k];
        }
    }
}

// ---------------- 4. per-row 8-way heads merge -> final top-10 ------------------
__global__ void topk_merge_kernel(int side) {
    __shared__ int cv[64 * 80];
    __shared__ int ci[64 * 80];
    int b = blockIdx.x, t = threadIdx.x;  // 64 threads
    int row0 = b * 64;
    for (int i = t; i < 64 * 80; i += 64) {
        cv[i] = g_candV[side][(size_t)row0 * 80 + i];
        ci[i] = g_candI[side][(size_t)row0 * 80 + i];
    }
    __syncthreads();
    const int* v = cv + t * 80;
    const int* id = ci + t * 80;
    int cur[8];
    #pragma unroll
    for (int h = 0; h < 8; ++h) cur[h] = h * 10;
    for (int k = 0; k < NN; ++k) {
        int best = (int)0x80000000; int bi = 0x7fffffff; int bh = 0;
        #pragma unroll
        for (int h = 0; h < 8; ++h) {
            int c = cur[h];
            if (c < h * 10 + 10) {
                int x = v[c];
                int xi = id[c];
                if (x > best || (x == best && xi < bi)) { best = x; bi = xi; bh = h; }
            }
        }
        g_topk[side][(row0 + t) * NN + k] = bi;
        #pragma unroll
        for (int h = 0; h < 8; ++h) cur[h] += (h == bh);
    }
}

// ---------------- 5. gather neighbor columns (exact fp32) -----------------------
__global__ void gather_kernel(int side, const float* __restrict__ qX,
                              const float* __restrict__ qY) {
    int j = blockIdx.x * 256 + threadIdx.x;
    int d = blockIdx.y;
    const float* Q = side ? qX : qY;
    int c = g_topk[side][j];
    g_nnT[side][d * BN + j] = Q[(size_t)d * Rk + c];
}

// ---------------- 6. stage-2 logits GEMM + fixed-max partial LSE ----------------
#define FP 132
#define SM2_F 0
#define SM2_J (64 * FP)
#define SM2_S (SM2_J + 128 * 64)
#define SM2_P (SM2_S + 64)
#define SMEM2_BYTES ((SM2_P + 64) * 4)

__global__ void __launch_bounds__(256, 3) lse_gemm_kernel(int side) {
    extern __shared__ float s2m[];
    float* F = s2m + SM2_F;
    float* J = s2m + SM2_J;
    float* accS = s2m + SM2_S;
    float* accP = s2m + SM2_P;
    int t = threadIdx.x;
    int tx = t & 15, ty = t >> 4;
    int rg = blockIdx.x, jb = blockIdx.y;

    {
        const float* feat = g_feat[side] + rg * 64 * Dk;
        for (int i = t; i < 64 * Dk; i += 256) {
            int r = i >> 7, d = i & 127;
            F[r * FP + d] = feat[i];
        }
        if (t < 64) { accS[t] = 0.f; accP[t] = 0.f; }
    }
    __syncthreads();

    const float4* nn4 = reinterpret_cast<const float4*>(g_nnT[side]);
    for (int jt = 0; jt < JW / 64; ++jt) {
        float4* J4 = reinterpret_cast<float4*>(J);
        #pragma unroll
        for (int i = 0; i < 8; ++i) {
            int lin = i * 256 + t;
            int d = lin >> 4, c4 = lin & 15;
            J4[d * 16 + c4] = nn4[(size_t)d * (BN / 4) + jb * (JW / 4) + jt * 16 + c4];
        }
        __syncthreads();

        u64 acc[4][2];
        #pragma unroll
        for (int r = 0; r < 4; ++r) { acc[r][0] = 0ull; acc[r][1] = 0ull; }
        const float* fb = F + (ty * 4) * FP;
        #pragma unroll 8
        for (int d = 0; d < Dk; ++d) {
            ulonglong2 q = *reinterpret_cast<const ulonglong2*>(J + d * 64 + tx * 4);
            #pragma unroll
            for (int r = 0; r < 4; ++r) {
                u64 fd = dupf(fb[r * FP + d]);
                ffma2(acc[r][0], q.x, fd);
                ffma2(acc[r][1], q.y, fd);
            }
        }

        int j0 = jb * JW + jt * 64 + tx * 4;
        #pragma unroll
        for (int r = 0; r < 4; ++r) {
            float2 a = unpack2(acc[r][0]);
            float2 b2 = unpack2(acc[r][1]);
            float vv[4] = { a.x, a.y, b2.x, b2.y };
            int rowg = rg * 64 + ty * 4 + r;
            float sE = 0.f, sP = 0.f;
            #pragma unroll
            for (int i = 0; i < 4; ++i) {
                float lg = vv[i] * 10.f;            // / TEMP
                sE += __expf(lg - 10.f);            // fixed max = 10 (cos<=1)
                unsigned dj = (unsigned)(j0 + i - rowg * NN);
                if (dj < (unsigned)NN) sP += lg;
            }
            #pragma unroll
            for (int o = 8; o; o >>= 1) {
                sE += __shfl_xor_sync(0xFFFFFFFFu, sE, o);
                sP += __shfl_xor_sync(0xFFFFFFFFu, sP, o);
            }
            if (tx == 0) { accS[ty * 4 + r] += sE; accP[ty * 4 + r] += sP; }
        }
        __syncthreads();
    }
    if (t < 64) {
        int rowg = rg * 64 + t;
        g_pS[side][rowg][jb] = accS[t];
        g_pP[side][rowg][jb] = accP[t];
    }
}

// ---------------- 7. combine partials -> loss ------------------------------------
__global__ void combine_kernel(float* __restrict__ out) {
    __shared__ float red[1024];
    int t = threadIdx.x;
    float term = 0.f;
    #pragma unroll
    for (int side = 0; side < 2; ++side) {
        float S = 0.f, P = 0.f;
        #pragma unroll
        for (int jb = 0; jb < JBLK; ++jb) { S += g_pS[side][t][jb]; P += g_pP[side][t][jb]; }
        term += P - (float)NN * (10.f + logf(S));
    }
    red[t] = term;
    __syncthreads();
    for (int s = 512; s; s >>= 1) {
        if (t < s) red[t] += red[t + s];
        __syncthreads();
    }
    if (t == 0) out[0] = -red[0] / (float)Bk;
}

// ---------------- 8. queue head columns ------------------------------------------
__global__ void qhead_kernel(float* __restrict__ out) {
    int c = blockIdx.x * 256 + threadIdx.x;
    int d = blockIdx.y;
    int side = blockIdx.z;
    out[1 + (size_t)side * Dk * Rk + (size_t)d * Rk + c] = g_feat[side][c * Dk + d];
}

// ---------------- launch: per-side pipelining across 3 streams -------------------
extern "C" void kernel_launch(void* const* d_in, const int* in_sizes, int n_in,
                              void* d_out, int out_size) {
    const float* fX = (const float*)d_in[0];
    const float* fY = (const float*)d_in[1];
    const float* qX = (const float*)d_in[2];
    const float* qY = (const float*)d_in[3];
    float* out = (float*)d_out;

    static cudaStream_t s1 = nullptr, s2 = nullptr;
    static cudaEvent_t evFork, evNorm, evT1, evS0, evL0, evSide;
    if (s1 == nullptr) {
        cudaStreamCreateWithFlags(&s1, cudaStreamNonBlocking);
        cudaStreamCreateWithFlags(&s2, cudaStreamNonBlocking);
        cudaEventCreateWithFlags(&evFork, cudaEventDisableTiming);
        cudaEventCreateWithFlags(&evNorm, cudaEventDisableTiming);
        cudaEventCreateWithFlags(&evT1, cudaEventDisableTiming);
        cudaEventCreateWithFlags(&evS0, cudaEventDisableTiming);
        cudaEventCreateWithFlags(&evL0, cudaEventDisableTiming);
        cudaEventCreateWithFlags(&evSide, cudaEventDisableTiming);
        cudaFuncSetAttribute(simtopk_i8_kernel,
                             cudaFuncAttributeMaxDynamicSharedMemorySize, SMEM1);
        cudaFuncSetAttribute(lse_gemm_kernel,
                             cudaFuncAttributeMaxDynamicSharedMemorySize, SMEM2_BYTES);
    }

    // fork side streams
    cudaEventRecord(evFork, 0);
    cudaStreamWaitEvent(s1, evFork, 0);
    cudaStreamWaitEvent(s2, evFork, 0);

    // s1: normalize, side-1 queue quantize, bulk copies, queue-head overwrite
    normalize_kernel<<<dim3(Bk, 2, 1), Dk, 0, s1>>>(fX, fY);
    cudaEventRecord(evNorm, s1);
    transposeQ_kernel<<<dim3(Rk / 32, Dk / 32, 1), dim3(32, 8, 1), 0, s1>>>(1, qX, qY);
    cudaEventRecord(evT1, s1);
    cudaMemcpyAsync(out + 1, qX, (size_t)Dk * Rk * sizeof(float),
                    cudaMemcpyDeviceToDevice, s1);
    cudaMemcpyAsync(out + 1 + (size_t)Dk * Rk, qY, (size_t)Dk * Rk * sizeof(float),
                    cudaMemcpyDeviceToDevice, s1);
    qhead_kernel<<<dim3(Bk / 256, Dk, 2), 256, 0, s1>>>(out);
    cudaEventRecord(evSide, s1);

    // main stream: side-0 queue quantize -> simtopk(0) -> simtopk(1)
    transposeQ_kernel<<<dim3(Rk / 32, Dk / 32, 1), dim3(32, 8, 1)>>>(0, qX, qY);
    cudaStreamWaitEvent(0, evNorm, 0);
    simtopk_i8_kernel<<<dim3(RNG, Bk / 64, 1), 256, SMEM1>>>(0);
    cudaEventRecord(evS0, 0);
    cudaStreamWaitEvent(0, evT1, 0);
    simtopk_i8_kernel<<<dim3(RNG, Bk / 64, 1), 256, SMEM1>>>(1);

    // s2: side-0 tail overlapped with simtopk(1)
    cudaStreamWaitEvent(s2, evS0, 0);
    topk_merge_kernel<<<dim3(Bk / 64, 1, 1), 64, 0, s2>>>(0);
    gather_kernel<<<dim3(BN / 256, Dk, 1), 256, 0, s2>>>(0, qX, qY);
    lse_gemm_kernel<<<dim3(Bk / 64, JBLK, 1), 256, SMEM2_BYTES, s2>>>(0);
    cudaEventRecord(evL0, s2);

    // main stream: side-1 tail, then combine after both sides' LSE
    topk_merge_kernel<<<dim3(Bk / 64, 1, 1), 64>>>(1);
    gather_kernel<<<dim3(BN / 256, Dk, 1), 256>>>(1, qX, qY);
    lse_gemm_kernel<<<dim3(Bk / 64, JBLK, 1), 256, SMEM2_BYTES>>>(1);
    cudaStreamWaitEvent(0, evL0, 0);
    combine_kernel<<<1, 1024>>>(out);

    // join copy stream
    cudaStreamWaitEvent(0, evSide, 0);
}

// round 17
// speedup vs baseline: 1.4436x; 1.4436x over previous
#include <cuda_runtime.h>
#include <cstdint>
#include <math.h>

#define Dk 128
#define Bk 1024
#define Rk 131072
#define NN 10
#define BN (Bk * NN)          // 10240
#define RNG 8                 // column ranges (stage-1 grid.x)
#define RSPAN (Rk / RNG)      // 16384 cols per CTA
#define SUB 128               // cols per sub-chunk
#define NSUB (RSPAN / SUB)    // 128
#define JBLK 16               // stage-2 j blocks
#define JW 640                // j per stage-2 block
#define QSCALE 254.0f         // fixed queue quant scale (127 / 0.5)

typedef unsigned long long u64;
typedef unsigned int u32;
typedef unsigned short u16;

// ---------------- device scratch ----------------
__device__ float g_feat[2][Bk * Dk];          // normalized fp32 feats [row][d]
__device__ u32   g_featQ[2][Bk * 32];         // int8 feats packed [row][kc]
__device__ u32   g_qQ[2][32][Rk];             // int8 queue packed [kc][r]
__device__ int   g_candV[2][Bk * RNG * NN];   // int top-10 values (sorted desc)
__device__ int   g_candI[2][Bk * RNG * NN];   // matching global col ids
__device__ int   g_topk[2][Bk * NN];
__device__ float g_nnT[2][Dk * BN];           // gathered fp32 [d][j]
__device__ float g_pS[2][Bk][JBLK];
__device__ float g_pP[2][Bk][JBLK];

// ---------------- helpers ----------------
__device__ __forceinline__ void ffma2(u64 &d, u64 a, u64 b) {
    asm("fma.rn.f32x2 %0, %1, %2, %0;" : "+l"(d) : "l"(a), "l"(b));
}
__device__ __forceinline__ u64 dupf(float f) {
    u64 r; unsigned u = __float_as_uint(f);
    asm("mov.b64 %0, {%1, %2};" : "=l"(r) : "r"(u), "r"(u));
    return r;
}
__device__ __forceinline__ float2 unpack2(u64 a) {
    float2 o;
    asm("mov.b64 {%0, %1}, %2;" : "=f"(o.x), "=f"(o.y) : "l"(a));
    return o;
}
__device__ __forceinline__ u32 smem_u32(const void* p) {
    u32 a;
    asm("{ .reg .u64 t; cvta.to.shared.u64 t, %1; cvt.u32.u64 %0, t; }"
        : "=r"(a) : "l"(p));
    return a;
}
#define CP_ASYNC16(sdst, gsrc) \
    asm volatile("cp.async.cg.shared.global [%0], [%1], 16;" \
                 :: "r"(sdst), "l"(gsrc) : "memory")
#define CP_COMMIT() asm volatile("cp.async.commit_group;" ::: "memory")
#define CP_WAIT0()  asm volatile("cp.async.wait_group 0;" ::: "memory")

// ---------------- 1. normalize rows + int8 pack ---------------------------------
__global__ void normalize_kernel(const float* __restrict__ fX,
                                 const float* __restrict__ fY) {
    int side = blockIdx.y;
    int row = blockIdx.x;
    int d = threadIdx.x;
    const float* in = side ? fY : fX;
    float v = in[row * Dk + d];
    float sq = v * v;
    #pragma unroll
    for (int o = 16; o; o >>= 1) sq += __shfl_xor_sync(0xFFFFFFFFu, sq, o);
    __shared__ float ws[4], wm[4];
    __shared__ float nrm, smx;
    __shared__ unsigned char sb8[128];
    if ((d & 31) == 0) ws[d >> 5] = sq;
    __syncthreads();
    if (d == 0) nrm = sqrtf(ws[0] + ws[1] + ws[2] + ws[3]);
    __syncthreads();
    float nv = v / nrm;
    g_feat[side][row * Dk + d] = nv;
    float av = fabsf(nv);
    #pragma unroll
    for (int o = 16; o; o >>= 1) av = fmaxf(av, __shfl_xor_sync(0xFFFFFFFFu, av, o));
    if ((d & 31) == 0) wm[d >> 5] = av;
    __syncthreads();
    if (d == 0) smx = fmaxf(fmaxf(wm[0], wm[1]), fmaxf(wm[2], wm[3]));
    __syncthreads();
    int q = __float2int_rn(nv * (127.f / smx));
    sb8[d] = (unsigned char)(signed char)q;
    __syncthreads();
    if (d < 32) {
        u32 p = (u32)sb8[4 * d] | ((u32)sb8[4 * d + 1] << 8) |
                ((u32)sb8[4 * d + 2] << 16) | ((u32)sb8[4 * d + 3] << 24);
        g_featQ[side][row * 32 + d] = p;   // [row][kc]
    }
}

// ---------------- 2. transpose + fixed-scale int8 quantize queue ----------------
__global__ void transposeQ_kernel(int side, const float* __restrict__ qX,
                                  const float* __restrict__ qY) {
    const float* src = side ? qX : qY;   // side 0 (feat X) uses queue_Y
    __shared__ float tile[32][33];
    int r0 = blockIdx.x * 32, d0 = blockIdx.y * 32;
    int tx = threadIdx.x, ty = threadIdx.y;
    #pragma unroll
    for (int i = 0; i < 4; ++i)
        tile[ty + i * 8][tx] = src[(size_t)(d0 + ty + i * 8) * Rk + r0 + tx];
    __syncthreads();
    u32 p = 0;
    #pragma unroll
    for (int b = 0; b < 4; ++b) {
        float v = fminf(fmaxf(tile[ty * 4 + b][tx] * QSCALE, -127.f), 127.f);
        int q = __float2int_rn(v);
        p |= ((u32)(unsigned char)(signed char)q) << (8 * b);
    }
    g_qQ[side][(d0 >> 2) + ty][r0 + tx] = p;
}

// ---------------- 3. DP4A sim GEMM + int Ss redistribution top-10 ---------------
#define S_QS 0                        // Qs u32 [2][32][128] = 32768 B
#define S_AS 32768                    // As u32 [64][32]     = 8192 B
#define S_SS 40960                    // Ss int [64][132]    = 33792 B
#define S_CV 74752                    // Cv int [256][10]    = 10240 B
#define S_CI 84992                    // Ci u16 [256][10]    = 5120 B
#define SMEM1 90112
#define SP1 132

__global__ void __launch_bounds__(256, 2) simtopk_i8_kernel() {
    extern __shared__ char sm[];
    u32 sb = smem_u32(sm);
    u32* Qs = reinterpret_cast<u32*>(sm + S_QS);
    u32* As = reinterpret_cast<u32*>(sm + S_AS);
    int* Ss = reinterpret_cast<int*>(sm + S_SS);
    int* Cv = reinterpret_cast<int*>(sm + S_CV);
    u16* Ci = reinterpret_cast<u16*>(sm + S_CI);
    int t = threadIdx.x, tx = t & 15, ty = t >> 4;
    int range = blockIdx.x, rt = blockIdx.y, side = blockIdx.z;
    int colBase = range * RSPAN;

    // A tile: [64 rows][32 kc] contiguous copy
    {
        const uint4* src = reinterpret_cast<const uint4*>(&g_featQ[side][rt * 64 * 32]);
        reinterpret_cast<uint4*>(As)[t] = src[t];
        reinterpret_cast<uint4*>(As)[t + 256] = src[t + 256];
    }
    // init persistent lists: thread owns (row = t>>2, seg = t&3)
    int* myCv = Cv + t * 10;
    u16* myCi = Ci + t * 10;
    #pragma unroll
    for (int k = 0; k < NN; ++k) { myCv[k] = (int)0x80000000; myCi[k] = 0; }
    int tv9 = (int)0x80000000;

    // cp.async slot mapping: 4 x 16B of Qs per thread
    int kcA = t >> 3;
    int c4A = (t * 4) & 31;
    const char* gQbase = reinterpret_cast<const char*>(&g_qQ[side][0][0]);
    size_t qRowStride = (size_t)Rk * 4;
    u32 sQ0 = sb + S_QS + (u32)(kcA * 512 + c4A * 16);

    // prologue: tile 0 -> buf 0
    {
        const char* gsrc = gQbase + (size_t)kcA * qRowStride +
                           (size_t)(colBase + c4A * 4) * 4;
        #pragma unroll
        for (int j = 0; j < 4; ++j) CP_ASYNC16(sQ0 + j * 16, gsrc + j * 16);
        CP_COMMIT();
    }

    int row = t >> 2, seg = t & 3;
    const int* scanBase = Ss + row * SP1 + seg * 32;

    for (int sc = 0; sc < NSUB; ++sc) {
        CP_WAIT0();
        __syncthreads();   // tile sc visible; prev scan's Ss reads done

        // prefetch tile sc+1 into alternate buffer (overlaps mainloop)
        if (sc + 1 < NSUB) {
            const char* gsrc = gQbase + (size_t)kcA * qRowStride +
                               (size_t)(colBase + (sc + 1) * SUB + c4A * 4) * 4;
            u32 sdst = sQ0 + (u32)(((sc + 1) & 1) * 16384);
            #pragma unroll
            for (int j = 0; j < 4; ++j) CP_ASYNC16(sdst + j * 16, gsrc + j * 16);
        }
        CP_COMMIT();

        const u32* Qb = Qs + (sc & 1) * 4096;

        // mainloop: 4 rows x 8 cols, A via LDS.128 broadcast
        int acc[4][8];
        #pragma unroll
        for (int r = 0; r < 4; ++r)
            #pragma unroll
            for (int c = 0; c < 8; ++c) acc[r][c] = 0;

        #pragma unroll 2
        for (int k4 = 0; k4 < 8; ++k4) {
            uint4 a4[4];
            #pragma unroll
            for (int r = 0; r < 4; ++r)
                a4[r] = *reinterpret_cast<const uint4*>(As + (ty * 4 + r) * 32 + k4 * 4);
            #pragma unroll
            for (int kk = 0; kk < 4; ++kk) {
                const u32* qp = Qb + (k4 * 4 + kk) * 128 + tx * 4;
                uint4 q0 = *reinterpret_cast<const uint4*>(qp);
                uint4 q1 = *reinterpret_cast<const uint4*>(qp + 64);
                #pragma unroll
                for (int r = 0; r < 4; ++r) {
                    int f = (int)((kk == 0) ? a4[r].x : (kk == 1) ? a4[r].y
                                 : (kk == 2) ? a4[r].z : a4[r].w);
                    acc[r][0] = __dp4a((int)q0.x, f, acc[r][0]);
                    acc[r][1] = __dp4a((int)q0.y, f, acc[r][1]);
                    acc[r][2] = __dp4a((int)q0.z, f, acc[r][2]);
                    acc[r][3] = __dp4a((int)q0.w, f, acc[r][3]);
                    acc[r][4] = __dp4a((int)q1.x, f, acc[r][4]);
                    acc[r][5] = __dp4a((int)q1.y, f, acc[r][5]);
                    acc[r][6] = __dp4a((int)q1.z, f, acc[r][6]);
                    acc[r][7] = __dp4a((int)q1.w, f, acc[r][7]);
                }
            }
        }

        // write raw int accumulators to Ss (8 STS.128)
        #pragma unroll
        for (int g = 0; g < 2; ++g)
            #pragma unroll
            for (int r = 0; r < 4; ++r) {
                int4 w = make_int4(acc[r][g * 4 + 0], acc[r][g * 4 + 1],
                                   acc[r][g * 4 + 2], acc[r][g * 4 + 3]);
                *reinterpret_cast<int4*>(Ss + (ty * 4 + r) * SP1 + g * 64 + tx * 4) = w;
            }
        __syncthreads();   // Ss visible

        // scan: contiguous 32 cols via 8 LDS.128 + quad-max prefilter
        {
            int cb = sc * SUB + seg * 32;
            #pragma unroll
            for (int qd = 0; qd < 8; ++qd) {
                int4 v = *reinterpret_cast<const int4*>(scanBase + qd * 4);
                int m01 = max(v.x, v.y), m23 = max(v.z, v.w);
                if (max(m01, m23) > tv9) {
                    int vv[4] = { v.x, v.y, v.z, v.w };
                    #pragma unroll
                    for (int e = 0; e < 4; ++e) {
                        int val = vv[e];
                        if (val > tv9) {
                            u16 col = (u16)(cb + qd * 4 + e);
                            int pp = 9;
                            while (pp > 0 && myCv[pp - 1] < val) {
                                myCv[pp] = myCv[pp - 1]; myCi[pp] = myCi[pp - 1]; --pp;
                            }
                            myCv[pp] = val; myCi[pp] = col;
                            tv9 = myCv[9];
                        }
                    }
                }
            }
        }
    }
    __syncthreads();

    // merge 4 seg-lists per row -> sorted top-10 -> g_cand (scratch in Qs)
    if (t < 64) {
        int* mv = reinterpret_cast<int*>(Qs) + t * 16;
        int* mi = reinterpret_cast<int*>(Qs) + 1024 + t * 16;
        #pragma unroll
        for (int k = 0; k < NN; ++k) { mv[k] = (int)0x80000000; mi[k] = 0x7fffffff; }
        int m9 = (int)0x80000000; int i9 = 0x7fffffff;
        for (int s = 0; s < 4; ++s) {
            const int* l = Cv + (t * 4 + s) * 10;
            const u16* li = Ci + (t * 4 + s) * 10;
            #pragma unroll
            for (int k = 0; k < NN; ++k) {
                int v = l[k];
                if (v < m9) break;
                int id = (int)li[k];
                if (v == m9 && id >= i9) continue;
                int pp = 9;
                while (pp > 0 && (mv[pp - 1] < v ||
                                  (mv[pp - 1] == v && mi[pp - 1] > id))) {
                    mv[pp] = mv[pp - 1]; mi[pp] = mi[pp - 1]; --pp;
                }
                mv[pp] = v; mi[pp] = id;
                m9 = mv[9]; i9 = mi[9];
            }
        }
        size_t gb = (((size_t)(rt * 64 + t) * RNG) + range) * NN;
        #pragma unroll
        for (int k = 0; k < NN; ++k) {
            g_candV[side][gb + k] = mv[k];
            g_candI[side][gb + k] = colBase + mi[k];
        }
    }
}

// ---------------- 4. per-row 8-way heads merge -> final top-10 ------------------
__global__ void topk_merge_kernel() {
    __shared__ int cv[64 * 80];
    __shared__ int ci[64 * 80];
    int b = blockIdx.x, side = blockIdx.y, t = threadIdx.x;  // 64 threads
    int row0 = b * 64;
    for (int i = t; i < 64 * 80; i += 64) {
        cv[i] = g_candV[side][(size_t)row0 * 80 + i];
        ci[i] = g_candI[side][(size_t)row0 * 80 + i];
    }
    __syncthreads();
    const int* v = cv + t * 80;
    const int* id = ci + t * 80;
    int cur[8];
    #pragma unroll
    for (int h = 0; h < 8; ++h) cur[h] = h * 10;
    for (int k = 0; k < NN; ++k) {
        int best = (int)0x80000000; int bi = 0x7fffffff; int bh = 0;
        #pragma unroll
        for (int h = 0; h < 8; ++h) {
            int c = cur[h];
            if (c < h * 10 + 10) {
                int x = v[c];
                int xi = id[c];
                if (x > best || (x == best && xi < bi)) { best = x; bi = xi; bh = h; }
            }
        }
        g_topk[side][(row0 + t) * NN + k] = bi;
        #pragma unroll
        for (int h = 0; h < 8; ++h) cur[h] += (h == bh);
    }
}

// ---------------- 5. gather neighbor columns (exact fp32) -----------------------
__global__ void gather_kernel(const float* __restrict__ qX,
                              const float* __restrict__ qY) {
    int j = blockIdx.x * 256 + threadIdx.x;
    int d = blockIdx.y;
    int side = blockIdx.z;
    const float* Q = side ? qX : qY;
    int c = g_topk[side][j];
    g_nnT[side][d * BN + j] = Q[(size_t)d * Rk + c];
}

// ---------------- 6. stage-2 logits GEMM + fixed-max partial LSE ----------------
#define FP 132
#define SM2_F 0
#define SM2_J (64 * FP)
#define SM2_S (SM2_J + 128 * 64)
#define SM2_P (SM2_S + 64)
#define SMEM2_BYTES ((SM2_P + 64) * 4)

__global__ void __launch_bounds__(256, 3) lse_gemm_kernel() {
    extern __shared__ float s2m[];
    float* F = s2m + SM2_F;
    float* J = s2m + SM2_J;
    float* accS = s2m + SM2_S;
    float* accP = s2m + SM2_P;
    int t = threadIdx.x;
    int tx = t & 15, ty = t >> 4;
    int rg = blockIdx.x, jb = blockIdx.y, side = blockIdx.z;

    {
        const float* feat = g_feat[side] + rg * 64 * Dk;
        for (int i = t; i < 64 * Dk; i += 256) {
            int r = i >> 7, d = i & 127;
            F[r * FP + d] = feat[i];
        }
        if (t < 64) { accS[t] = 0.f; accP[t] = 0.f; }
    }
    __syncthreads();

    const float4* nn4 = reinterpret_cast<const float4*>(g_nnT[side]);
    for (int jt = 0; jt < JW / 64; ++jt) {
        float4* J4 = reinterpret_cast<float4*>(J);
        #pragma unroll
        for (int i = 0; i < 8; ++i) {
            int lin = i * 256 + t;
            int d = lin >> 4, c4 = lin & 15;
            J4[d * 16 + c4] = nn4[(size_t)d * (BN / 4) + jb * (JW / 4) + jt * 16 + c4];
        }
        __syncthreads();

        u64 acc[4][2];
        #pragma unroll
        for (int r = 0; r < 4; ++r) { acc[r][0] = 0ull; acc[r][1] = 0ull; }
        const float* fb = F + (ty * 4) * FP;
        #pragma unroll 8
        for (int d = 0; d < Dk; ++d) {
            ulonglong2 q = *reinterpret_cast<const ulonglong2*>(J + d * 64 + tx * 4);
            #pragma unroll
            for (int r = 0; r < 4; ++r) {
                u64 fd = dupf(fb[r * FP + d]);
                ffma2(acc[r][0], q.x, fd);
                ffma2(acc[r][1], q.y, fd);
            }
        }

        int j0 = jb * JW + jt * 64 + tx * 4;
        #pragma unroll
        for (int r = 0; r < 4; ++r) {
            float2 a = unpack2(acc[r][0]);
            float2 b2 = unpack2(acc[r][1]);
            float vv[4] = { a.x, a.y, b2.x, b2.y };
            int rowg = rg * 64 + ty * 4 + r;
            float sE = 0.f, sP = 0.f;
            #pragma unroll
            for (int i = 0; i < 4; ++i) {
                float lg = vv[i] * 10.f;            // / TEMP
                sE += __expf(lg - 10.f);            // fixed max = 10 (cos<=1)
                unsigned dj = (unsigned)(j0 + i - rowg * NN);
                if (dj < (unsigned)NN) sP += lg;
            }
            #pragma unroll
            for (int o = 8; o; o >>= 1) {
                sE += __shfl_xor_sync(0xFFFFFFFFu, sE, o);
                sP += __shfl_xor_sync(0xFFFFFFFFu, sP, o);
            }
            if (tx == 0) { accS[ty * 4 + r] += sE; accP[ty * 4 + r] += sP; }
        }
        __syncthreads();
    }
    if (t < 64) {
        int rowg = rg * 64 + t;
        g_pS[side][rowg][jb] = accS[t];
        g_pP[side][rowg][jb] = accP[t];
    }
}

// ---------------- 7. combine partials -> loss ------------------------------------
__global__ void combine_kernel(float* __restrict__ out) {
    __shared__ float red[1024];
    int t = threadIdx.x;
    float term = 0.f;
    #pragma unroll
    for (int side = 0; side < 2; ++side) {
        float S = 0.f, P = 0.f;
        #pragma unroll
        for (int jb = 0; jb < JBLK; ++jb) { S += g_pS[side][t][jb]; P += g_pP[side][t][jb]; }
        term += P - (float)NN * (10.f + logf(S));
    }
    red[t] = term;
    __syncthreads();
    for (int s = 512; s; s >>= 1) {
        if (t < s) red[t] += red[t + s];
        __syncthreads();
    }
    if (t == 0) out[0] = -red[0] / (float)Bk;
}

// ---------------- 8. queue head columns ------------------------------------------
__global__ void qhead_kernel(float* __restrict__ out) {
    int c = blockIdx.x * 256 + threadIdx.x;
    int d = blockIdx.y;
    int side = blockIdx.z;
    out[1 + (size_t)side * Dk * Rk + (size_t)d * Rk + c] = g_feat[side][c * Dk + d];
}

// ---------------- launch: R14 schedule + split transposeQ ------------------------
extern "C" void kernel_launch(void* const* d_in, const int* in_sizes, int n_in,
                              void* d_out, int out_size) {
    const float* fX = (const float*)d_in[0];
    const float* fY = (const float*)d_in[1];
    const float* qX = (const float*)d_in[2];
    const float* qY = (const float*)d_in[3];
    float* out = (float*)d_out;

    static cudaStream_t s1 = nullptr;
    static cudaEvent_t evFork, evNorm, evT1, evSide;
    if (s1 == nullptr) {
        cudaStreamCreateWithFlags(&s1, cudaStreamNonBlocking);
        cudaEventCreateWithFlags(&evFork, cudaEventDisableTiming);
        cudaEventCreateWithFlags(&evNorm, cudaEventDisableTiming);
        cudaEventCreateWithFlags(&evT1, cudaEventDisableTiming);
        cudaEventCreateWithFlags(&evSide, cudaEventDisableTiming);
        cudaFuncSetAttribute(simtopk_i8_kernel,
                             cudaFuncAttributeMaxDynamicSharedMemorySize, SMEM1);
        cudaFuncSetAttribute(lse_gemm_kernel,
                             cudaFuncAttributeMaxDynamicSharedMemorySize, SMEM2_BYTES);
    }

    // fork side stream off the capture/legacy stream
    cudaEventRecord(evFork, 0);
    cudaStreamWaitEvent(s1, evFork, 0);

    // s1: normalize -> side-1 quantize -> bulk copies -> queue-head overwrite
    normalize_kernel<<<dim3(Bk, 2, 1), Dk, 0, s1>>>(fX, fY);
    transposeQ_kernel<<<dim3(Rk / 32, Dk / 32, 1), dim3(32, 8, 1), 0, s1>>>(1, qX, qY);
    cudaEventRecord(evNorm, s1);   // normalize + transposeQ(1) both done
    cudaMemcpyAsync(out + 1, qX, (size_t)Dk * Rk * sizeof(float),
                    cudaMemcpyDeviceToDevice, s1);
    cudaMemcpyAsync(out + 1 + (size_t)Dk * Rk, qY, (size_t)Dk * Rk * sizeof(float),
                    cudaMemcpyDeviceToDevice, s1);
    qhead_kernel<<<dim3(Bk / 256, Dk, 2), 256, 0, s1>>>(out);
    cudaEventRecord(evSide, s1);

    // main stream: side-0 quantize runs concurrently with s1's work
    transposeQ_kernel<<<dim3(Rk / 32, Dk / 32, 1), dim3(32, 8, 1)>>>(0, qX, qY);
    cudaStreamWaitEvent(0, evNorm, 0);   // need g_featQ + g_qQ[1]

    simtopk_i8_kernel<<<dim3(RNG, Bk / 64, 2), 256, SMEM1>>>();
    topk_merge_kernel<<<dim3(Bk / 64, 2, 1), 64>>>();
    gather_kernel<<<dim3(BN / 256, Dk, 2), 256>>>(qX, qY);
    lse_gemm_kernel<<<dim3(Bk / 64, JBLK, 2), 256, SMEM2_BYTES>>>();
    combine_kernel<<<1, 1024>>>(out);

    // join side stream before returning
    cudaStreamWaitEvent(0, evSide, 0);
}